// round 9
// baseline (speedup 1.0000x reference)
#include <cuda_runtime.h>
#include <cuda_bf16.h>
#include <cstdint>

#define D_MODEL 1024
#define NH 16
#define DH 64
#define SEQ 2048
#define BATCH 2
#define BH (BATCH * NH)        // 32
#define M_ROWS (BATCH * SEQ)   // 4096
#define N_QKV (3 * NH * DH)    // 3072

// Scratch (bf16 pairs 16B-aligned for cp.async; g_A / g_QKV fp32)
__device__ __align__(16) __nv_bfloat16 g_Xhi[(size_t)M_ROWS * D_MODEL];
__device__ __align__(16) __nv_bfloat16 g_Xlo[(size_t)M_ROWS * D_MODEL];
__device__ __align__(16) __nv_bfloat16 g_Wqh[(size_t)N_QKV * D_MODEL];   // [n][k]
__device__ __align__(16) __nv_bfloat16 g_Wql[(size_t)N_QKV * D_MODEL];
__device__ __align__(16) float g_QKV[(size_t)M_ROWS * N_QKV];
__device__ __align__(16) __nv_bfloat16 g_Qhi[(size_t)BH * SEQ * DH];
__device__ __align__(16) __nv_bfloat16 g_Qlo[(size_t)BH * SEQ * DH];
__device__ __align__(16) __nv_bfloat16 g_Khi[(size_t)BH * SEQ * DH];
__device__ __align__(16) __nv_bfloat16 g_Klo[(size_t)BH * SEQ * DH];
__device__ __align__(16) __nv_bfloat16 g_Vthi[(size_t)BH * DH * SEQ];
__device__ __align__(16) __nv_bfloat16 g_Vtlo[(size_t)BH * DH * SEQ];
__device__ float g_A[(size_t)M_ROWS * D_MODEL];

// ---------------------------------------------------------------------------
__device__ __forceinline__ float exp2_fast(float x)
{
    x = fmaxf(x, -80.0f);
    float z = x + 12582912.0f;
    int   n = __float_as_int(z) - 0x4B400000;
    float f = x - (z - 12582912.0f);
    float p = 1.3369700e-3f;
    p = fmaf(p, f, 9.6179365e-3f);
    p = fmaf(p, f, 5.5503264e-2f);
    p = fmaf(p, f, 2.4022736e-1f);
    p = fmaf(p, f, 6.9314693e-1f);
    p = fmaf(p, f, 1.0f);
    return __int_as_float(__float_as_int(p) + (n << 23));
}

__device__ __forceinline__ uint32_t smem_u32(const void* p) {
    uint32_t a;
    asm("{ .reg .u64 t; cvta.to.shared.u64 t, %1; cvt.u32.u64 %0, t; }"
        : "=r"(a) : "l"(p));
    return a;
}

// returns {second arg in bits 31:16, first arg in bits 15:0}
__device__ __forceinline__ uint32_t pack_bf16(float lo_elem, float hi_elem) {
    uint32_t r;
    asm("cvt.rn.bf16x2.f32 %0, %1, %2;" : "=r"(r) : "f"(hi_elem), "f"(lo_elem));
    return r;
}

__device__ __forceinline__ float bf16_rnf(float x) {
    return __bfloat162float(__float2bfloat16(x));
}

__device__ __forceinline__ void mma_bf16(float* c, const uint32_t* a,
                                         uint32_t b0, uint32_t b1) {
    asm volatile(
        "mma.sync.aligned.m16n8k16.row.col.f32.bf16.bf16.f32 "
        "{%0,%1,%2,%3}, {%4,%5,%6,%7}, {%8,%9}, {%0,%1,%2,%3};"
        : "+f"(c[0]), "+f"(c[1]), "+f"(c[2]), "+f"(c[3])
        : "r"(a[0]), "r"(a[1]), "r"(a[2]), "r"(a[3]), "r"(b0), "r"(b1));
}

#define CP_ASYNC16(dst, src) \
    asm volatile("cp.async.cg.shared.global [%0], [%1], 16;" \
                 :: "r"(dst), "l"(src))
#define CP_COMMIT() asm volatile("cp.async.commit_group;" ::: "memory")
#define CP_WAIT0()  asm volatile("cp.async.wait_group 0;" ::: "memory")
#define CP_WAIT1()  asm volatile("cp.async.wait_group 1;" ::: "memory")

// ---------------------------------------------------------------------------
// Split fp32 -> bf16 hi/lo (elementwise)
// ---------------------------------------------------------------------------
__global__ __launch_bounds__(256) void split_plain(
    const float* __restrict__ src, __nv_bfloat16* __restrict__ hi,
    __nv_bfloat16* __restrict__ lo, int n4)
{
    int i = blockIdx.x * 256 + threadIdx.x;
    if (i >= n4) return;
    float4 v = *(const float4*)(src + (size_t)i * 4);
    uint2 h, l;
    h.x = pack_bf16(v.x, v.y);
    h.y = pack_bf16(v.z, v.w);
    l.x = pack_bf16(v.x - bf16_rnf(v.x), v.y - bf16_rnf(v.y));
    l.y = pack_bf16(v.z - bf16_rnf(v.z), v.w - bf16_rnf(v.w));
    *(uint2*)(hi + (size_t)i * 4) = h;
    *(uint2*)(lo + (size_t)i * 4) = l;
}

// ---------------------------------------------------------------------------
// Transpose + split: W[k][n] fp32 -> hi/lo [n][k] bf16
// ---------------------------------------------------------------------------
template <int N>
__global__ __launch_bounds__(256) void transpose_split(
    const float* __restrict__ src, __nv_bfloat16* __restrict__ hi,
    __nv_bfloat16* __restrict__ lo)
{
    __shared__ float tile[32][33];
    int tx = threadIdx.x, ty = threadIdx.y;
    int n0 = blockIdx.x * 32, k0 = blockIdx.y * 32;
    #pragma unroll
    for (int i = 0; i < 4; i++) {
        int r = ty * 4 + i;
        tile[r][tx] = src[(size_t)(k0 + r) * N + n0 + tx];
    }
    __syncthreads();
    #pragma unroll
    for (int i = 0; i < 4; i++) {
        int rn = ty * 4 + i;
        float v = tile[tx][rn];
        size_t idx = (size_t)(n0 + rn) * D_MODEL + k0 + tx;
        __nv_bfloat16 h = __float2bfloat16(v);
        hi[idx] = h;
        lo[idx] = __float2bfloat16(v - __bfloat162float(h));
    }
}

// ---------------------------------------------------------------------------
// Shared geometry (proven in flash_attn_mma): 4 tensors x 64 rows x 72 bf16,
// double buffered = 73728 B, block = 128 threads (4 warps).
// ---------------------------------------------------------------------------
#define TSTRIDE 72
#define TBYTES  (64 * TSTRIDE * 2)      // 9216
#define STAGEB  (4 * TBYTES)            // 36864
#define SMEM_STAGE2 (2 * STAGEB)        // 73728

// ---------------------------------------------------------------------------
// QKV GEMM — same mma loop as R8, but with flash's SIMPLE linear epilogue
// (float2 fp32 stores to g_QKV). Tests the "scatter epilogue poisons the
// accumulators" hypothesis.
// grid: (N_QKV/64, M_ROWS/64) = (48, 64), block 128.
// ---------------------------------------------------------------------------
__global__ __launch_bounds__(128) void qkv_gemm_mma(
    const __nv_bfloat16* __restrict__ Ahi, const __nv_bfloat16* __restrict__ Alo,
    const __nv_bfloat16* __restrict__ Bhi, const __nv_bfloat16* __restrict__ Blo)
{
    extern __shared__ char sm[];
    const uint32_t smb = smem_u32(sm);

    const int tid  = threadIdx.x;
    const int warp = tid >> 5;
    const int lane = tid & 31;
    const int g    = lane >> 2;
    const int lt   = lane & 3;
    const int n0   = blockIdx.x * 64;
    const int m0   = blockIdx.y * 64;

    float acc[8][4];
    #pragma unroll
    for (int i = 0; i < 8; i++)
        #pragma unroll
        for (int j = 0; j < 4; j++) acc[i][j] = 0.0f;

    auto load_stage = [&](int buf, int k0) {
        #pragma unroll
        for (int it = 0; it < 16; it++) {
            int i = tid + it * 128;
            int tensor = i >> 9;
            int rem = i & 511;
            int row = rem >> 3;
            int c8  = rem & 7;
            const __nv_bfloat16* src;
            if (tensor == 0)      src = Ahi + (size_t)(m0 + row) * D_MODEL + k0 + c8 * 8;
            else if (tensor == 1) src = Alo + (size_t)(m0 + row) * D_MODEL + k0 + c8 * 8;
            else if (tensor == 2) src = Bhi + (size_t)(n0 + row) * D_MODEL + k0 + c8 * 8;
            else                  src = Blo + (size_t)(n0 + row) * D_MODEL + k0 + c8 * 8;
            uint32_t dst = smb + buf * STAGEB + tensor * TBYTES
                         + row * (TSTRIDE * 2) + c8 * 16;
            CP_ASYNC16(dst, src);
        }
        CP_COMMIT();
    };

    load_stage(0, 0);

    const int NC = D_MODEL / 64;   // 16 chunks
    for (int t = 0; t < NC; t++) {
        if (t + 1 < NC) { load_stage((t + 1) & 1, (t + 1) * 64); }
        if (t + 1 < NC) { CP_WAIT1(); } else { CP_WAIT0(); }
        __syncthreads();

        const int bb = t & 1;
        const __nv_bfloat16* sAh = (const __nv_bfloat16*)(sm + bb*STAGEB);
        const __nv_bfloat16* sAl = (const __nv_bfloat16*)(sm + bb*STAGEB + TBYTES);
        const __nv_bfloat16* sBh = (const __nv_bfloat16*)(sm + bb*STAGEB + 2*TBYTES);
        const __nv_bfloat16* sBl = (const __nv_bfloat16*)(sm + bb*STAGEB + 3*TBYTES);

        uint32_t aAh[16], aAl[16];
        #pragma unroll
        for (int kg = 0; kg < 4; kg++) {
            int r0 = (warp * 16 + g) * TSTRIDE + kg * 16 + 2 * lt;
            int r8 = r0 + 8 * TSTRIDE;
            aAh[4*kg+0] = *(const uint32_t*)(sAh + r0);
            aAh[4*kg+1] = *(const uint32_t*)(sAh + r8);
            aAh[4*kg+2] = *(const uint32_t*)(sAh + r0 + 8);
            aAh[4*kg+3] = *(const uint32_t*)(sAh + r8 + 8);
            aAl[4*kg+0] = *(const uint32_t*)(sAl + r0);
            aAl[4*kg+1] = *(const uint32_t*)(sAl + r8);
            aAl[4*kg+2] = *(const uint32_t*)(sAl + r0 + 8);
            aAl[4*kg+3] = *(const uint32_t*)(sAl + r8 + 8);
        }

        #pragma unroll
        for (int nf = 0; nf < 8; nf++) {
            #pragma unroll
            for (int kg = 0; kg < 4; kg++) {
                int off = (nf * 8 + g) * TSTRIDE + kg * 16 + 2 * lt;
                uint32_t b0h = *(const uint32_t*)(sBh + off);
                uint32_t b1h = *(const uint32_t*)(sBh + off + 8);
                uint32_t b0l = *(const uint32_t*)(sBl + off);
                uint32_t b1l = *(const uint32_t*)(sBl + off + 8);
                mma_bf16(acc[nf], &aAh[4*kg], b0h, b1h);
                mma_bf16(acc[nf], &aAh[4*kg], b0l, b1l);
                mma_bf16(acc[nf], &aAl[4*kg], b0h, b1h);
            }
        }
        __syncthreads();
    }

    // ---- SIMPLE epilogue (flash-shaped): linear float2 stores ----
    const int m_g  = m0 + warp * 16 + g;
    const int m_g8 = m_g + 8;
    #pragma unroll
    for (int nf = 0; nf < 8; nf++) {
        int n = n0 + nf * 8 + 2 * lt;
        float2 u, w;
        u.x = acc[nf][0]; u.y = acc[nf][1];
        w.x = acc[nf][2]; w.y = acc[nf][3];
        *(float2*)(g_QKV + (size_t)m_g  * N_QKV + n) = u;
        *(float2*)(g_QKV + (size_t)m_g8 * N_QKV + n) = w;
    }
}

// ---------------------------------------------------------------------------
// Elementwise scatter: g_QKV[m][c] -> Q/K/V bf16 hi/lo (de-interleave (h,d,3),
// Q scaled by 0.125*log2e, V transposed). One thread per (m, triplet).
// ---------------------------------------------------------------------------
__global__ __launch_bounds__(256) void qkv_scatter()
{
    int j = blockIdx.x * 256 + threadIdx.x;       // 0 .. M_ROWS*1024-1
    int m = j >> 10;
    int t = j & 1023;
    int h = t >> 6;
    int dd = t & 63;
    const float QSCALE = 0.18033688011112042f;    // 0.125 * log2(e)

    const float* p = g_QKV + (size_t)m * N_QKV + t * 3;
    float q = p[0] * QSCALE;
    float k = p[1];
    float v = p[2];

    int b = m >> 11;
    int s = m & 2047;
    size_t iqk = (((size_t)(b * NH + h)) * SEQ + s) * DH + dd;
    size_t iv  = (((size_t)(b * NH + h)) * DH + dd) * SEQ + s;

    __nv_bfloat16 qh = __float2bfloat16(q);
    g_Qhi[iqk] = qh;
    g_Qlo[iqk] = __float2bfloat16(q - __bfloat162float(qh));
    __nv_bfloat16 kh = __float2bfloat16(k);
    g_Khi[iqk] = kh;
    g_Klo[iqk] = __float2bfloat16(k - __bfloat162float(kh));
    __nv_bfloat16 vh = __float2bfloat16(v);
    g_Vthi[iv] = vh;
    g_Vtlo[iv] = __float2bfloat16(v - __bfloat162float(vh));
}

// ---------------------------------------------------------------------------
// Flash attention via mma.sync m16n8k16 bf16 (R5 VERBATIM — proven).
// ---------------------------------------------------------------------------
__global__ __launch_bounds__(128) void flash_attn_mma()
{
    extern __shared__ char sm[];
    const uint32_t smb = smem_u32(sm);

    const int tid  = threadIdx.x;
    const int warp = tid >> 5;
    const int lane = tid & 31;
    const int g    = lane >> 2;
    const int lt   = lane & 3;
    const int bh   = blockIdx.x;
    const int q0   = blockIdx.y * 64;

    uint32_t aQh[16], aQl[16];
    {
        const size_t qb = (size_t)bh * SEQ + q0 + warp * 16;
        const __nv_bfloat16* Qh0 = g_Qhi + (qb + g) * DH;
        const __nv_bfloat16* Qh8 = g_Qhi + (qb + g + 8) * DH;
        const __nv_bfloat16* Ql0 = g_Qlo + (qb + g) * DH;
        const __nv_bfloat16* Ql8 = g_Qlo + (qb + g + 8) * DH;
        #pragma unroll
        for (int kg = 0; kg < 4; kg++) {
            int d0 = kg * 16 + 2 * lt;
            aQh[4*kg+0] = *(const uint32_t*)(Qh0 + d0);
            aQh[4*kg+1] = *(const uint32_t*)(Qh8 + d0);
            aQh[4*kg+2] = *(const uint32_t*)(Qh0 + d0 + 8);
            aQh[4*kg+3] = *(const uint32_t*)(Qh8 + d0 + 8);
            aQl[4*kg+0] = *(const uint32_t*)(Ql0 + d0);
            aQl[4*kg+1] = *(const uint32_t*)(Ql8 + d0);
            aQl[4*kg+2] = *(const uint32_t*)(Ql0 + d0 + 8);
            aQl[4*kg+3] = *(const uint32_t*)(Ql8 + d0 + 8);
        }
    }

    float O[8][4];
    #pragma unroll
    for (int i = 0; i < 8; i++)
        #pragma unroll
        for (int j = 0; j < 4; j++) O[i][j] = 0.0f;
    float m0 = -1e30f, m1 = -1e30f, l0 = 0.0f, l1 = 0.0f;

    const __nv_bfloat16* baseKh = g_Khi + (size_t)bh * SEQ * DH;
    const __nv_bfloat16* baseKl = g_Klo + (size_t)bh * SEQ * DH;
    const __nv_bfloat16* baseVh = g_Vthi + (size_t)bh * DH * SEQ;
    const __nv_bfloat16* baseVl = g_Vtlo + (size_t)bh * DH * SEQ;

    auto load_stage = [&](int buf, int kt) {
        #pragma unroll
        for (int it = 0; it < 16; it++) {
            int i = tid + it * 128;
            int tensor = i >> 9;
            int rem = i & 511;
            int row = rem >> 3;
            int c8  = rem & 7;
            const __nv_bfloat16* src;
            if (tensor == 0)      src = baseKh + (size_t)(kt + row) * DH + c8 * 8;
            else if (tensor == 1) src = baseKl + (size_t)(kt + row) * DH + c8 * 8;
            else if (tensor == 2) src = baseVh + (size_t)row * SEQ + kt + c8 * 8;
            else                  src = baseVl + (size_t)row * SEQ + kt + c8 * 8;
            uint32_t dst = smb + buf * STAGEB + tensor * TBYTES
                         + row * (TSTRIDE * 2) + c8 * 16;
            CP_ASYNC16(dst, src);
        }
        CP_COMMIT();
    };

    load_stage(0, 0);

    const int NT = SEQ / 64;
    for (int t = 0; t < NT; t++) {
        if (t + 1 < NT) { load_stage((t + 1) & 1, (t + 1) * 64); }
        if (t + 1 < NT) { CP_WAIT1(); } else { CP_WAIT0(); }
        __syncthreads();

        const int bb = t & 1;
        const __nv_bfloat16* sKhi = (const __nv_bfloat16*)(sm + bb*STAGEB);
        const __nv_bfloat16* sKlo = (const __nv_bfloat16*)(sm + bb*STAGEB + TBYTES);
        const __nv_bfloat16* sVhi = (const __nv_bfloat16*)(sm + bb*STAGEB + 2*TBYTES);
        const __nv_bfloat16* sVlo = (const __nv_bfloat16*)(sm + bb*STAGEB + 3*TBYTES);

        float s[8][4];
        #pragma unroll
        for (int i = 0; i < 8; i++)
            #pragma unroll
            for (int j = 0; j < 4; j++) s[i][j] = 0.0f;

        #pragma unroll
        for (int nf = 0; nf < 8; nf++) {
            #pragma unroll
            for (int kg = 0; kg < 4; kg++) {
                int off = (nf * 8 + g) * TSTRIDE + kg * 16 + 2 * lt;
                uint32_t b0h = *(const uint32_t*)(sKhi + off);
                uint32_t b1h = *(const uint32_t*)(sKhi + off + 8);
                uint32_t b0l = *(const uint32_t*)(sKlo + off);
                uint32_t b1l = *(const uint32_t*)(sKlo + off + 8);
                mma_bf16(s[nf], &aQh[4*kg], b0h, b1h);
                mma_bf16(s[nf], &aQh[4*kg], b0l, b1l);
                mma_bf16(s[nf], &aQl[4*kg], b0h, b1h);
            }
        }

        float r0 = -1e30f, r1 = -1e30f;
        #pragma unroll
        for (int nf = 0; nf < 8; nf++) {
            r0 = fmaxf(r0, fmaxf(s[nf][0], s[nf][1]));
            r1 = fmaxf(r1, fmaxf(s[nf][2], s[nf][3]));
        }
        r0 = fmaxf(r0, __shfl_xor_sync(0xffffffffu, r0, 1));
        r0 = fmaxf(r0, __shfl_xor_sync(0xffffffffu, r0, 2));
        r1 = fmaxf(r1, __shfl_xor_sync(0xffffffffu, r1, 1));
        r1 = fmaxf(r1, __shfl_xor_sync(0xffffffffu, r1, 2));

        float mn0 = fmaxf(m0, r0), mn1 = fmaxf(m1, r1);
        float cr0 = exp2_fast(m0 - mn0), cr1 = exp2_fast(m1 - mn1);
        m0 = mn0; m1 = mn1;
        l0 *= cr0; l1 *= cr1;
        #pragma unroll
        for (int i = 0; i < 8; i++) {
            O[i][0] *= cr0; O[i][1] *= cr0;
            O[i][2] *= cr1; O[i][3] *= cr1;
        }

        uint32_t phi[16], plo[16];
        #pragma unroll
        for (int nf = 0; nf < 8; nf++) {
            float p0 = exp2_fast(s[nf][0] - m0);
            float p1 = exp2_fast(s[nf][1] - m0);
            float p2 = exp2_fast(s[nf][2] - m1);
            float p3 = exp2_fast(s[nf][3] - m1);
            l0 += p0 + p1;
            l1 += p2 + p3;
            phi[2*nf+0] = pack_bf16(p0, p1);
            phi[2*nf+1] = pack_bf16(p2, p3);
            plo[2*nf+0] = pack_bf16(p0 - bf16_rnf(p0), p1 - bf16_rnf(p1));
            plo[2*nf+1] = pack_bf16(p2 - bf16_rnf(p2), p3 - bf16_rnf(p3));
        }

        #pragma unroll
        for (int nfd = 0; nfd < 8; nfd++) {
            #pragma unroll
            for (int kg = 0; kg < 4; kg++) {
                int off = (nfd * 8 + g) * TSTRIDE + kg * 16 + 2 * lt;
                uint32_t b0h = *(const uint32_t*)(sVhi + off);
                uint32_t b1h = *(const uint32_t*)(sVhi + off + 8);
                uint32_t b0l = *(const uint32_t*)(sVlo + off);
                uint32_t b1l = *(const uint32_t*)(sVlo + off + 8);
                mma_bf16(O[nfd], &phi[4*kg], b0h, b1h);
                mma_bf16(O[nfd], &phi[4*kg], b0l, b1l);
                mma_bf16(O[nfd], &plo[4*kg], b0h, b1h);
            }
        }
        __syncthreads();
    }

    l0 += __shfl_xor_sync(0xffffffffu, l0, 1);
    l0 += __shfl_xor_sync(0xffffffffu, l0, 2);
    l1 += __shfl_xor_sync(0xffffffffu, l1, 1);
    l1 += __shfl_xor_sync(0xffffffffu, l1, 2);

    float i0 = 1.0f / l0, i1 = 1.0f / l1;
    int b  = bh >> 4;
    int hh = bh & 15;
    int qr0 = q0 + warp * 16 + g;
    int qr1 = qr0 + 8;
    float* A0 = g_A + (((size_t)b * SEQ + qr0) * NH + hh) * DH;
    float* A1 = g_A + (((size_t)b * SEQ + qr1) * NH + hh) * DH;
    #pragma unroll
    for (int nfd = 0; nfd < 8; nfd++) {
        int d = nfd * 8 + 2 * lt;
        float2 u, w;
        u.x = O[nfd][0] * i0; u.y = O[nfd][1] * i0;
        w.x = O[nfd][2] * i1; w.y = O[nfd][3] * i1;
        *(float2*)(A0 + d) = u;
        *(float2*)(A1 + d) = w;
    }
}

// ---------------------------------------------------------------------------
// GEMM 2: out = g_A[4096,1024] @ W_out[1024,1024]  (R5 SIMT VERBATIM — proven)
// ---------------------------------------------------------------------------
__global__ __launch_bounds__(256) void out_gemm_kernel(
    const float* __restrict__ B, float* __restrict__ C)
{
    const int K = D_MODEL;
    const int N = D_MODEL;
    const float* A = g_A;
    __shared__ float As[16][132];
    __shared__ float Bs[16][128];

    int tid = threadIdx.x;
    int bm = blockIdx.y * 128;
    int bn = blockIdx.x * 128;

    int a_row = tid >> 2;
    int a_col = (tid & 3) << 2;
    int b_row = tid >> 5;
    int b_col = (tid & 31) << 2;

    int tx = tid & 15;
    int ty = tid >> 4;

    float acc[8][8] = {};

    const float* Aptr  = A + (size_t)(bm + a_row) * K + a_col;
    const float* Aptr2 = Aptr + (size_t)64 * K;
    const float* Bptr  = B + (size_t)b_row * N + bn + b_col;

    for (int k0 = 0; k0 < K; k0 += 16) {
        float4 a0 = *(const float4*)(Aptr  + k0);
        float4 a1 = *(const float4*)(Aptr2 + k0);
        float4 b0 = *(const float4*)(Bptr + (size_t)k0 * N);
        float4 b1 = *(const float4*)(Bptr + (size_t)(k0 + 8) * N);

        As[a_col + 0][a_row] = a0.x;
        As[a_col + 1][a_row] = a0.y;
        As[a_col + 2][a_row] = a0.z;
        As[a_col + 3][a_row] = a0.w;
        As[a_col + 0][a_row + 64] = a1.x;
        As[a_col + 1][a_row + 64] = a1.y;
        As[a_col + 2][a_row + 64] = a1.z;
        As[a_col + 3][a_row + 64] = a1.w;
        *(float4*)&Bs[b_row][b_col]     = b0;
        *(float4*)&Bs[b_row + 8][b_col] = b1;
        __syncthreads();

        #pragma unroll
        for (int k = 0; k < 16; k++) {
            float af[8], bf[8];
            *(float4*)&af[0] = *(const float4*)&As[k][ty * 8];
            *(float4*)&af[4] = *(const float4*)&As[k][ty * 8 + 4];
            *(float4*)&bf[0] = *(const float4*)&Bs[k][tx * 8];
            *(float4*)&bf[4] = *(const float4*)&Bs[k][tx * 8 + 4];
            #pragma unroll
            for (int i = 0; i < 8; i++)
                #pragma unroll
                for (int j = 0; j < 8; j++)
                    acc[i][j] += af[i] * bf[j];
        }
        __syncthreads();
    }

    #pragma unroll
    for (int i = 0; i < 8; i++) {
        int m = bm + ty * 8 + i;
        float* Cp = C + (size_t)m * N + bn + tx * 8;
        float4 v0, v1;
        v0.x = acc[i][0]; v0.y = acc[i][1]; v0.z = acc[i][2]; v0.w = acc[i][3];
        v1.x = acc[i][4]; v1.y = acc[i][5]; v1.z = acc[i][6]; v1.w = acc[i][7];
        *(float4*)Cp       = v0;
        *(float4*)(Cp + 4) = v1;
    }
}

extern "C" void kernel_launch(void* const* d_in, const int* in_sizes, int n_in,
                              void* d_out, int out_size)
{
    const float* X     = (const float*)d_in[0];
    const float* W_qkv = (const float*)d_in[1];
    const float* W_out = (const float*)d_in[2];
    float* out = (float*)d_out;

    cudaFuncSetAttribute(flash_attn_mma,
                         cudaFuncAttributeMaxDynamicSharedMemorySize, SMEM_STAGE2);
    cudaFuncSetAttribute(qkv_gemm_mma,
                         cudaFuncAttributeMaxDynamicSharedMemorySize, SMEM_STAGE2);

    split_plain<<<(M_ROWS * D_MODEL / 4 + 255) / 256, 256>>>(
        X, g_Xhi, g_Xlo, M_ROWS * D_MODEL / 4);
    transpose_split<N_QKV><<<dim3(N_QKV / 32, D_MODEL / 32), dim3(32, 8)>>>(
        W_qkv, g_Wqh, g_Wql);

    qkv_gemm_mma<<<dim3(N_QKV / 64, M_ROWS / 64), 128, SMEM_STAGE2>>>(
        g_Xhi, g_Xlo, g_Wqh, g_Wql);

    qkv_scatter<<<(M_ROWS * 1024) / 256, 256>>>();

    flash_attn_mma<<<dim3(BH, SEQ / 64), 128, SMEM_STAGE2>>>();

    out_gemm_kernel<<<dim3(D_MODEL / 128, M_ROWS / 128), 256>>>(W_out, out);
}

// round 10
// speedup vs baseline: 13.2607x; 13.2607x over previous
#include <cuda_runtime.h>
#include <cuda_bf16.h>
#include <cstdint>

#define D_MODEL 1024
#define NH 16
#define DH 64
#define SEQ 2048
#define BATCH 2
#define BH (BATCH * NH)        // 32
#define M_ROWS (BATCH * SEQ)   // 4096
#define N_QKV (3 * NH * DH)    // 3072

// Scratch. Q/K: [bh][s][d] bf16 hi/lo. V transposed: [bh][d][s] hi/lo.
__device__ __align__(16) __nv_bfloat16 g_Qhi[(size_t)BH * SEQ * DH];
__device__ __align__(16) __nv_bfloat16 g_Qlo[(size_t)BH * SEQ * DH];
__device__ __align__(16) __nv_bfloat16 g_Khi[(size_t)BH * SEQ * DH];
__device__ __align__(16) __nv_bfloat16 g_Klo[(size_t)BH * SEQ * DH];
__device__ __align__(16) __nv_bfloat16 g_Vthi[(size_t)BH * DH * SEQ];
__device__ __align__(16) __nv_bfloat16 g_Vtlo[(size_t)BH * DH * SEQ];
__device__ float g_A[(size_t)M_ROWS * D_MODEL];

// ---------------------------------------------------------------------------
// Packed fp32x2 helpers (Blackwell FFMA2 — 2 IEEE fp32 FMAs per instruction)
// ---------------------------------------------------------------------------
#define PACK_F32X2(out, lo, hi) \
    asm("mov.b64 %0, {%1, %2};" : "=l"(out) : "f"(lo), "f"(hi))
#define UNPACK_F32X2(lo, hi, in) \
    asm("mov.b64 {%0, %1}, %2;" : "=f"(lo), "=f"(hi) : "l"(in))
#define FMA_F32X2(acc, a, b) \
    asm("fma.rn.f32x2 %0, %1, %2, %0;" : "+l"(acc) : "l"(a), "l"(b))

// ---------------------------------------------------------------------------
__device__ __forceinline__ float exp2_fast(float x)
{
    x = fmaxf(x, -80.0f);
    float z = x + 12582912.0f;
    int   n = __float_as_int(z) - 0x4B400000;
    float f = x - (z - 12582912.0f);
    float p = 1.3369700e-3f;
    p = fmaf(p, f, 9.6179365e-3f);
    p = fmaf(p, f, 5.5503264e-2f);
    p = fmaf(p, f, 2.4022736e-1f);
    p = fmaf(p, f, 6.9314693e-1f);
    p = fmaf(p, f, 1.0f);
    return __int_as_float(__float_as_int(p) + (n << 23));
}

__device__ __forceinline__ uint32_t smem_u32(const void* p) {
    uint32_t a;
    asm("{ .reg .u64 t; cvta.to.shared.u64 t, %1; cvt.u32.u64 %0, t; }"
        : "=r"(a) : "l"(p));
    return a;
}

// returns {second arg in bits 31:16, first arg in bits 15:0}
__device__ __forceinline__ uint32_t pack_bf16(float lo_elem, float hi_elem) {
    uint32_t r;
    asm("cvt.rn.bf16x2.f32 %0, %1, %2;" : "=r"(r) : "f"(hi_elem), "f"(lo_elem));
    return r;
}

__device__ __forceinline__ float bf16_rnf(float x) {
    return __bfloat162float(__float2bfloat16(x));
}

__device__ __forceinline__ void mma_bf16(float* c, const uint32_t* a,
                                         uint32_t b0, uint32_t b1) {
    asm volatile(
        "mma.sync.aligned.m16n8k16.row.col.f32.bf16.bf16.f32 "
        "{%0,%1,%2,%3}, {%4,%5,%6,%7}, {%8,%9}, {%0,%1,%2,%3};"
        : "+f"(c[0]), "+f"(c[1]), "+f"(c[2]), "+f"(c[3])
        : "r"(a[0]), "r"(a[1]), "r"(a[2]), "r"(a[3]), "r"(b0), "r"(b1));
}

#define CP_ASYNC16(dst, src) \
    asm volatile("cp.async.cg.shared.global [%0], [%1], 16;" \
                 :: "r"(dst), "l"(src))
#define CP_COMMIT() asm volatile("cp.async.commit_group;" ::: "memory")
#define CP_WAIT0()  asm volatile("cp.async.wait_group 0;" ::: "memory")
#define CP_WAIT1()  asm volatile("cp.async.wait_group 1;" ::: "memory")

// ---------------------------------------------------------------------------
// GEMM 1: qkv = X @ W_qkv (SIMT, f32x2 inner loop). Epilogue de-interleaves
// (h,d,3), scales Q by 0.125*log2e, splits to bf16 hi/lo, transposes V.
// (R5-proven structure; only the FMA loop is packed.)
// ---------------------------------------------------------------------------
__global__ __launch_bounds__(256) void qkv_gemm_kernel(
    const float* __restrict__ A, const float* __restrict__ B)
{
    const int K = D_MODEL;
    const int N = N_QKV;
    __shared__ float As[16][132];
    __shared__ float Bs[16][128];

    int tid = threadIdx.x;
    int bm = blockIdx.y * 128;
    int bn = blockIdx.x * 128;

    int a_row = tid >> 2;
    int a_col = (tid & 3) << 2;
    int b_row = tid >> 5;
    int b_col = (tid & 31) << 2;

    int tx = tid & 15;
    int ty = tid >> 4;

    unsigned long long acc2[8][4];
    #pragma unroll
    for (int i = 0; i < 8; i++)
        #pragma unroll
        for (int j = 0; j < 4; j++) acc2[i][j] = 0ull;

    const float* Aptr  = A + (size_t)(bm + a_row) * K + a_col;
    const float* Aptr2 = Aptr + (size_t)64 * K;
    const float* Bptr  = B + (size_t)b_row * N + bn + b_col;

    for (int k0 = 0; k0 < K; k0 += 16) {
        float4 a0 = *(const float4*)(Aptr  + k0);
        float4 a1 = *(const float4*)(Aptr2 + k0);
        float4 b0 = *(const float4*)(Bptr + (size_t)k0 * N);
        float4 b1 = *(const float4*)(Bptr + (size_t)(k0 + 8) * N);

        As[a_col + 0][a_row] = a0.x;
        As[a_col + 1][a_row] = a0.y;
        As[a_col + 2][a_row] = a0.z;
        As[a_col + 3][a_row] = a0.w;
        As[a_col + 0][a_row + 64] = a1.x;
        As[a_col + 1][a_row + 64] = a1.y;
        As[a_col + 2][a_row + 64] = a1.z;
        As[a_col + 3][a_row + 64] = a1.w;
        *(float4*)&Bs[b_row][b_col]     = b0;
        *(float4*)&Bs[b_row + 8][b_col] = b1;
        __syncthreads();

        #pragma unroll
        for (int k = 0; k < 16; k++) {
            float af[8], bf[8];
            *(float4*)&af[0] = *(const float4*)&As[k][ty * 8];
            *(float4*)&af[4] = *(const float4*)&As[k][ty * 8 + 4];
            *(float4*)&bf[0] = *(const float4*)&Bs[k][tx * 8];
            *(float4*)&bf[4] = *(const float4*)&Bs[k][tx * 8 + 4];
            unsigned long long b2[4];
            #pragma unroll
            for (int j2 = 0; j2 < 4; j2++)
                PACK_F32X2(b2[j2], bf[2 * j2], bf[2 * j2 + 1]);
            #pragma unroll
            for (int i = 0; i < 8; i++) {
                unsigned long long a2;
                PACK_F32X2(a2, af[i], af[i]);
                #pragma unroll
                for (int j2 = 0; j2 < 4; j2++)
                    FMA_F32X2(acc2[i][j2], a2, b2[j2]);
            }
        }
        __syncthreads();
    }

    const float QSCALE = 0.18033688011112042f;   // 0.125 * log2(e)
    #pragma unroll
    for (int i = 0; i < 8; i++) {
        float acc[8];
        #pragma unroll
        for (int j2 = 0; j2 < 4; j2++)
            UNPACK_F32X2(acc[2 * j2], acc[2 * j2 + 1], acc2[i][j2]);
        int m = bm + ty * 8 + i;
        int b = m >> 11;
        int s = m & 2047;
        #pragma unroll
        for (int j = 0; j < 8; j++) {
            int c = bn + tx * 8 + j;
            int r = c % 3;
            int h = c / 192;
            int dd = (c % 192) / 3;
            float x = acc[j];
            if (r == 0) x *= QSCALE;
            size_t idx;
            if (r == 2) idx = (((size_t)(b * NH + h)) * DH + dd) * SEQ + s;
            else        idx = (((size_t)(b * NH + h)) * SEQ + s) * DH + dd;
            __nv_bfloat16 hi = __float2bfloat16(x);
            __nv_bfloat16 lo = __float2bfloat16(x - __bfloat162float(hi));
            if (r == 0)      { g_Qhi[idx] = hi;  g_Qlo[idx] = lo; }
            else if (r == 1) { g_Khi[idx] = hi;  g_Klo[idx] = lo; }
            else             { g_Vthi[idx] = hi; g_Vtlo[idx] = lo; }
        }
    }
}

// ---------------------------------------------------------------------------
// Flash attention via mma.sync m16n8k16 bf16 (R5 VERBATIM — proven).
// ---------------------------------------------------------------------------
#define TSTRIDE 72
#define TBYTES  (64 * TSTRIDE * 2)
#define STAGEB  (4 * TBYTES)
#define SMEM_ATTN (2 * STAGEB)

__global__ __launch_bounds__(128) void flash_attn_mma()
{
    extern __shared__ char sm[];
    const uint32_t smb = smem_u32(sm);

    const int tid  = threadIdx.x;
    const int warp = tid >> 5;
    const int lane = tid & 31;
    const int g    = lane >> 2;
    const int lt   = lane & 3;
    const int bh   = blockIdx.x;
    const int q0   = blockIdx.y * 64;

    uint32_t aQh[16], aQl[16];
    {
        const size_t qb = (size_t)bh * SEQ + q0 + warp * 16;
        const __nv_bfloat16* Qh0 = g_Qhi + (qb + g) * DH;
        const __nv_bfloat16* Qh8 = g_Qhi + (qb + g + 8) * DH;
        const __nv_bfloat16* Ql0 = g_Qlo + (qb + g) * DH;
        const __nv_bfloat16* Ql8 = g_Qlo + (qb + g + 8) * DH;
        #pragma unroll
        for (int kg = 0; kg < 4; kg++) {
            int d0 = kg * 16 + 2 * lt;
            aQh[4*kg+0] = *(const uint32_t*)(Qh0 + d0);
            aQh[4*kg+1] = *(const uint32_t*)(Qh8 + d0);
            aQh[4*kg+2] = *(const uint32_t*)(Qh0 + d0 + 8);
            aQh[4*kg+3] = *(const uint32_t*)(Qh8 + d0 + 8);
            aQl[4*kg+0] = *(const uint32_t*)(Ql0 + d0);
            aQl[4*kg+1] = *(const uint32_t*)(Ql8 + d0);
            aQl[4*kg+2] = *(const uint32_t*)(Ql0 + d0 + 8);
            aQl[4*kg+3] = *(const uint32_t*)(Ql8 + d0 + 8);
        }
    }

    float O[8][4];
    #pragma unroll
    for (int i = 0; i < 8; i++)
        #pragma unroll
        for (int j = 0; j < 4; j++) O[i][j] = 0.0f;
    float m0 = -1e30f, m1 = -1e30f, l0 = 0.0f, l1 = 0.0f;

    const __nv_bfloat16* baseKh = g_Khi + (size_t)bh * SEQ * DH;
    const __nv_bfloat16* baseKl = g_Klo + (size_t)bh * SEQ * DH;
    const __nv_bfloat16* baseVh = g_Vthi + (size_t)bh * DH * SEQ;
    const __nv_bfloat16* baseVl = g_Vtlo + (size_t)bh * DH * SEQ;

    auto load_stage = [&](int buf, int kt) {
        #pragma unroll
        for (int it = 0; it < 16; it++) {
            int i = tid + it * 128;
            int tensor = i >> 9;
            int rem = i & 511;
            int row = rem >> 3;
            int c8  = rem & 7;
            const __nv_bfloat16* src;
            if (tensor == 0)      src = baseKh + (size_t)(kt + row) * DH + c8 * 8;
            else if (tensor == 1) src = baseKl + (size_t)(kt + row) * DH + c8 * 8;
            else if (tensor == 2) src = baseVh + (size_t)row * SEQ + kt + c8 * 8;
            else                  src = baseVl + (size_t)row * SEQ + kt + c8 * 8;
            uint32_t dst = smb + buf * STAGEB + tensor * TBYTES
                         + row * (TSTRIDE * 2) + c8 * 16;
            CP_ASYNC16(dst, src);
        }
        CP_COMMIT();
    };

    load_stage(0, 0);

    const int NT = SEQ / 64;
    for (int t = 0; t < NT; t++) {
        if (t + 1 < NT) { load_stage((t + 1) & 1, (t + 1) * 64); }
        if (t + 1 < NT) { CP_WAIT1(); } else { CP_WAIT0(); }
        __syncthreads();

        const int bb = t & 1;
        const __nv_bfloat16* sKhi = (const __nv_bfloat16*)(sm + bb*STAGEB);
        const __nv_bfloat16* sKlo = (const __nv_bfloat16*)(sm + bb*STAGEB + TBYTES);
        const __nv_bfloat16* sVhi = (const __nv_bfloat16*)(sm + bb*STAGEB + 2*TBYTES);
        const __nv_bfloat16* sVlo = (const __nv_bfloat16*)(sm + bb*STAGEB + 3*TBYTES);

        float s[8][4];
        #pragma unroll
        for (int i = 0; i < 8; i++)
            #pragma unroll
            for (int j = 0; j < 4; j++) s[i][j] = 0.0f;

        #pragma unroll
        for (int nf = 0; nf < 8; nf++) {
            #pragma unroll
            for (int kg = 0; kg < 4; kg++) {
                int off = (nf * 8 + g) * TSTRIDE + kg * 16 + 2 * lt;
                uint32_t b0h = *(const uint32_t*)(sKhi + off);
                uint32_t b1h = *(const uint32_t*)(sKhi + off + 8);
                uint32_t b0l = *(const uint32_t*)(sKlo + off);
                uint32_t b1l = *(const uint32_t*)(sKlo + off + 8);
                mma_bf16(s[nf], &aQh[4*kg], b0h, b1h);
                mma_bf16(s[nf], &aQh[4*kg], b0l, b1l);
                mma_bf16(s[nf], &aQl[4*kg], b0h, b1h);
            }
        }

        float r0 = -1e30f, r1 = -1e30f;
        #pragma unroll
        for (int nf = 0; nf < 8; nf++) {
            r0 = fmaxf(r0, fmaxf(s[nf][0], s[nf][1]));
            r1 = fmaxf(r1, fmaxf(s[nf][2], s[nf][3]));
        }
        r0 = fmaxf(r0, __shfl_xor_sync(0xffffffffu, r0, 1));
        r0 = fmaxf(r0, __shfl_xor_sync(0xffffffffu, r0, 2));
        r1 = fmaxf(r1, __shfl_xor_sync(0xffffffffu, r1, 1));
        r1 = fmaxf(r1, __shfl_xor_sync(0xffffffffu, r1, 2));

        float mn0 = fmaxf(m0, r0), mn1 = fmaxf(m1, r1);
        float cr0 = exp2_fast(m0 - mn0), cr1 = exp2_fast(m1 - mn1);
        m0 = mn0; m1 = mn1;
        l0 *= cr0; l1 *= cr1;
        #pragma unroll
        for (int i = 0; i < 8; i++) {
            O[i][0] *= cr0; O[i][1] *= cr0;
            O[i][2] *= cr1; O[i][3] *= cr1;
        }

        uint32_t phi[16], plo[16];
        #pragma unroll
        for (int nf = 0; nf < 8; nf++) {
            float p0 = exp2_fast(s[nf][0] - m0);
            float p1 = exp2_fast(s[nf][1] - m0);
            float p2 = exp2_fast(s[nf][2] - m1);
            float p3 = exp2_fast(s[nf][3] - m1);
            l0 += p0 + p1;
            l1 += p2 + p3;
            phi[2*nf+0] = pack_bf16(p0, p1);
            phi[2*nf+1] = pack_bf16(p2, p3);
            plo[2*nf+0] = pack_bf16(p0 - bf16_rnf(p0), p1 - bf16_rnf(p1));
            plo[2*nf+1] = pack_bf16(p2 - bf16_rnf(p2), p3 - bf16_rnf(p3));
        }

        #pragma unroll
        for (int nfd = 0; nfd < 8; nfd++) {
            #pragma unroll
            for (int kg = 0; kg < 4; kg++) {
                int off = (nfd * 8 + g) * TSTRIDE + kg * 16 + 2 * lt;
                uint32_t b0h = *(const uint32_t*)(sVhi + off);
                uint32_t b1h = *(const uint32_t*)(sVhi + off + 8);
                uint32_t b0l = *(const uint32_t*)(sVlo + off);
                uint32_t b1l = *(const uint32_t*)(sVlo + off + 8);
                mma_bf16(O[nfd], &phi[4*kg], b0h, b1h);
                mma_bf16(O[nfd], &phi[4*kg], b0l, b1l);
                mma_bf16(O[nfd], &plo[4*kg], b0h, b1h);
            }
        }
        __syncthreads();
    }

    l0 += __shfl_xor_sync(0xffffffffu, l0, 1);
    l0 += __shfl_xor_sync(0xffffffffu, l0, 2);
    l1 += __shfl_xor_sync(0xffffffffu, l1, 1);
    l1 += __shfl_xor_sync(0xffffffffu, l1, 2);

    float i0 = 1.0f / l0, i1 = 1.0f / l1;
    int b  = bh >> 4;
    int hh = bh & 15;
    int qr0 = q0 + warp * 16 + g;
    int qr1 = qr0 + 8;
    float* A0 = g_A + (((size_t)b * SEQ + qr0) * NH + hh) * DH;
    float* A1 = g_A + (((size_t)b * SEQ + qr1) * NH + hh) * DH;
    #pragma unroll
    for (int nfd = 0; nfd < 8; nfd++) {
        int d = nfd * 8 + 2 * lt;
        float2 u, w;
        u.x = O[nfd][0] * i0; u.y = O[nfd][1] * i0;
        w.x = O[nfd][2] * i1; w.y = O[nfd][3] * i1;
        *(float2*)(A0 + d) = u;
        *(float2*)(A1 + d) = w;
    }
}

// ---------------------------------------------------------------------------
// GEMM 2: out = g_A @ W_out (SIMT, f32x2 inner loop)
// ---------------------------------------------------------------------------
__global__ __launch_bounds__(256) void out_gemm_kernel(
    const float* __restrict__ B, float* __restrict__ C)
{
    const int K = D_MODEL;
    const int N = D_MODEL;
    const float* A = g_A;
    __shared__ float As[16][132];
    __shared__ float Bs[16][128];

    int tid = threadIdx.x;
    int bm = blockIdx.y * 128;
    int bn = blockIdx.x * 128;

    int a_row = tid >> 2;
    int a_col = (tid & 3) << 2;
    int b_row = tid >> 5;
    int b_col = (tid & 31) << 2;

    int tx = tid & 15;
    int ty = tid >> 4;

    unsigned long long acc2[8][4];
    #pragma unroll
    for (int i = 0; i < 8; i++)
        #pragma unroll
        for (int j = 0; j < 4; j++) acc2[i][j] = 0ull;

    const float* Aptr  = A + (size_t)(bm + a_row) * K + a_col;
    const float* Aptr2 = Aptr + (size_t)64 * K;
    const float* Bptr  = B + (size_t)b_row * N + bn + b_col;

    for (int k0 = 0; k0 < K; k0 += 16) {
        float4 a0 = *(const float4*)(Aptr  + k0);
        float4 a1 = *(const float4*)(Aptr2 + k0);
        float4 b0 = *(const float4*)(Bptr + (size_t)k0 * N);
        float4 b1 = *(const float4*)(Bptr + (size_t)(k0 + 8) * N);

        As[a_col + 0][a_row] = a0.x;
        As[a_col + 1][a_row] = a0.y;
        As[a_col + 2][a_row] = a0.z;
        As[a_col + 3][a_row] = a0.w;
        As[a_col + 0][a_row + 64] = a1.x;
        As[a_col + 1][a_row + 64] = a1.y;
        As[a_col + 2][a_row + 64] = a1.z;
        As[a_col + 3][a_row + 64] = a1.w;
        *(float4*)&Bs[b_row][b_col]     = b0;
        *(float4*)&Bs[b_row + 8][b_col] = b1;
        __syncthreads();

        #pragma unroll
        for (int k = 0; k < 16; k++) {
            float af[8], bf[8];
            *(float4*)&af[0] = *(const float4*)&As[k][ty * 8];
            *(float4*)&af[4] = *(const float4*)&As[k][ty * 8 + 4];
            *(float4*)&bf[0] = *(const float4*)&Bs[k][tx * 8];
            *(float4*)&bf[4] = *(const float4*)&Bs[k][tx * 8 + 4];
            unsigned long long b2[4];
            #pragma unroll
            for (int j2 = 0; j2 < 4; j2++)
                PACK_F32X2(b2[j2], bf[2 * j2], bf[2 * j2 + 1]);
            #pragma unroll
            for (int i = 0; i < 8; i++) {
                unsigned long long a2;
                PACK_F32X2(a2, af[i], af[i]);
                #pragma unroll
                for (int j2 = 0; j2 < 4; j2++)
                    FMA_F32X2(acc2[i][j2], a2, b2[j2]);
            }
        }
        __syncthreads();
    }

    #pragma unroll
    for (int i = 0; i < 8; i++) {
        float acc[8];
        #pragma unroll
        for (int j2 = 0; j2 < 4; j2++)
            UNPACK_F32X2(acc[2 * j2], acc[2 * j2 + 1], acc2[i][j2]);
        int m = bm + ty * 8 + i;
        float* Cp = C + (size_t)m * N + bn + tx * 8;
        float4 v0, v1;
        v0.x = acc[0]; v0.y = acc[1]; v0.z = acc[2]; v0.w = acc[3];
        v1.x = acc[4]; v1.y = acc[5]; v1.z = acc[6]; v1.w = acc[7];
        *(float4*)Cp       = v0;
        *(float4*)(Cp + 4) = v1;
    }
}

extern "C" void kernel_launch(void* const* d_in, const int* in_sizes, int n_in,
                              void* d_out, int out_size)
{
    const float* X     = (const float*)d_in[0];
    const float* W_qkv = (const float*)d_in[1];
    const float* W_out = (const float*)d_in[2];
    float* out = (float*)d_out;

    cudaFuncSetAttribute(flash_attn_mma,
                         cudaFuncAttributeMaxDynamicSharedMemorySize, SMEM_ATTN);

    qkv_gemm_kernel<<<dim3(N_QKV / 128, M_ROWS / 128), 256>>>(X, W_qkv);
    flash_attn_mma<<<dim3(BH, SEQ / 64), 128, SMEM_ATTN>>>();
    out_gemm_kernel<<<dim3(D_MODEL / 128, M_ROWS / 128), 256>>>(W_out, out);
}